// round 8
// baseline (speedup 1.0000x reference)
#include <cuda_runtime.h>

// ShortConv: depthwise causal conv1d, K=4.
// x: (B=4, S=4096, D=2048) fp32, weight: (D, 1, K) fp32, bias: (D,) fp32.
// y[b,s,d] = w[d,0]*x[b,s-3,d] + w[d,1]*x[b,s-2,d] + w[d,2]*x[b,s-1,d]
//          + w[d,3]*x[b,s,d] + bias[d]      (x indices < 0 are zero)
//
// HBM-streaming kernel: each thread owns one float4 of channels and marches
// over SCHUNK consecutive s positions with a 3-deep register sliding window
// (each x element loaded once; 3-load prologue hits L2).
// R3 change: y stores use st.global.cs (evict-first streaming) so the
// write-once output stream does not evict L2-resident x lines — x reuse
// (prologue overlap + cross-replay residency) stays in L2, cutting DRAM reads.

#define DIMC   2048
#define KSZ    4
#define BATCHC 4
#define SEQC   4096
#define D4     (DIMC / 4)   // 512 float4 channel-vectors per position
#define SCHUNK 16
#define TPB    256

__device__ __forceinline__ void store_streaming(float4* p, float4 v) {
    asm volatile("st.global.cs.v4.f32 [%0], {%1, %2, %3, %4};"
                 :: "l"(p), "f"(v.x), "f"(v.y), "f"(v.z), "f"(v.w)
                 : "memory");
}

__global__ __launch_bounds__(TPB) void shortconv_kernel(
    const float* __restrict__ x,
    const float* __restrict__ w,
    const float* __restrict__ bias,
    float* __restrict__ y)
{
    const int d4 = blockIdx.x * TPB + threadIdx.x;   // 0 .. D4-1
    const int s0 = blockIdx.y * SCHUNK;
    const int b  = blockIdx.z;

    const float4* __restrict__ xb =
        reinterpret_cast<const float4*>(x) + (size_t)b * SEQC * D4;
    float4* __restrict__ yb =
        reinterpret_cast<float4*>(y) + (size_t)b * SEQC * D4;

    // Per-channel taps: weight is (D,1,K) so channel c's 4 taps are one float4.
    const float4* __restrict__ wv = reinterpret_cast<const float4*>(w);
    const float4 wt0 = wv[d4 * 4 + 0];   // taps for channel 4*d4+0
    const float4 wt1 = wv[d4 * 4 + 1];
    const float4 wt2 = wv[d4 * 4 + 2];
    const float4 wt3 = wv[d4 * 4 + 3];
    const float4 bz  = reinterpret_cast<const float4*>(bias)[d4];

    // Sliding window: win0 = x[s-3], win1 = x[s-2], win2 = x[s-1]
    const float4 zero4 = make_float4(0.f, 0.f, 0.f, 0.f);
    float4 win0, win1, win2;
    {
        int sm3 = s0 - 3, sm2 = s0 - 2, sm1 = s0 - 1;
        win0 = (sm3 >= 0) ? xb[(size_t)sm3 * D4 + d4] : zero4;
        win1 = (sm2 >= 0) ? xb[(size_t)sm2 * D4 + d4] : zero4;
        win2 = (sm1 >= 0) ? xb[(size_t)sm1 * D4 + d4] : zero4;
    }

    #pragma unroll
    for (int i = 0; i < SCHUNK; ++i) {
        const int s = s0 + i;
        const float4 xs = xb[(size_t)s * D4 + d4];

        float4 o;
        o.x = fmaf(wt0.x, win0.x,
              fmaf(wt0.y, win1.x,
              fmaf(wt0.z, win2.x,
              fmaf(wt0.w, xs.x, bz.x))));
        o.y = fmaf(wt1.x, win0.y,
              fmaf(wt1.y, win1.y,
              fmaf(wt1.z, win2.y,
              fmaf(wt1.w, xs.y, bz.y))));
        o.z = fmaf(wt2.x, win0.z,
              fmaf(wt2.y, win1.z,
              fmaf(wt2.z, win2.z,
              fmaf(wt2.w, xs.z, bz.z))));
        o.w = fmaf(wt3.x, win0.w,
              fmaf(wt3.y, win1.w,
              fmaf(wt3.z, win2.w,
              fmaf(wt3.w, xs.w, bz.w))));

        store_streaming(&yb[(size_t)s * D4 + d4], o);

        win0 = win1;
        win1 = win2;
        win2 = xs;
    }
}

extern "C" void kernel_launch(void* const* d_in, const int* in_sizes, int n_in,
                              void* d_out, int out_size)
{
    const float* x    = (const float*)d_in[0];
    const float* w    = (const float*)d_in[1];
    const float* bias = (const float*)d_in[2];
    float* y          = (float*)d_out;

    dim3 block(TPB);
    dim3 grid(D4 / TPB, SEQC / SCHUNK, BATCHC);   // (2, 256, 4)
    shortconv_kernel<<<grid, block>>>(x, w, bias, y);
}